// round 17
// baseline (speedup 1.0000x reference)
#include <cuda_runtime.h>
#include <cuda_bf16.h>
#include <stdint.h>

// RayCastLayer R17: R16 champion (one 2-plane group per 112-thread CTA,
// full-line threads, register weights) pushed to 8 CTAs/SM (regs capped 71,
// grid 1024 <= 148*8 slots, single wave, 8 barrier domains per SM).

#define BOARD 19
#define NPOS  361
#define PW    55            // padded tile width (x shifted by +18)
#define TILE  (BOARD * PW)  // 1045 u64 entries
#define THREADS 112
#define PLANES 2

typedef unsigned long long u64;

#define FMA2(a, x, y) asm("fma.rn.f32x2 %0, %1, %2, %0;" : "+l"(a) : "l"(x), "l"(y))
#define ADD2(a, x)    asm("add.rn.f32x2 %0, %0, %1;"     : "+l"(a) : "l"(x))

__device__ __forceinline__ u64 dupf(float w) {
    u64 u;
    const uint32_t b = __float_as_uint(w);
    asm("mov.b64 %0, {%1,%1};" : "=l"(u) : "r"(b));
    return u;
}

__global__ __launch_bounds__(THREADS, 8)
void raycast_kernel(const float* __restrict__ x,
                    const float* __restrict__ weight,
                    float* __restrict__ out,
                    int nplanes)
{
    __shared__ u64 tile[TILE];             // [19][55], 2 planes as f32x2
    __shared__ u64 bufV[NPOS];             // per-family partials
    __shared__ u64 bufH[NPOS];
    __shared__ u64 bufD1[NPOS];
    __shared__ u64 bufD2[NPOS];

    const int tid = threadIdx.x;
    const int g0  = blockIdx.x * PLANES;

    // ---- zero lateral pad columns (disjoint from data fill) ----
    #pragma unroll
    for (int it = 0; it < 7; it++) {                  // 19*36 = 684 entries
        const int i = tid + it * THREADS;
        if (i < BOARD * 36) {
            const int y = i / 36;
            const int c = i - y * 36;
            const int col = (c < 18) ? c : (c + BOARD);   // [0,18) and [37,55)
            tile[y * PW + col] = 0ull;
        }
    }

    // ---- data fill: 4 unrolled rounds over 361 positions ----
    const bool full = (g0 + PLANES <= nplanes);
    const float* __restrict__ x0 = x + (size_t)g0 * NPOS;
    const float* __restrict__ x1 = x0 + NPOS;
    #pragma unroll
    for (int it = 0; it < 4; it++) {
        const int p = tid + it * THREADS;
        if (p < NPOS) {
            const int yy = p / BOARD;
            const int xx = p - yy * BOARD;
            float v0, v1;
            if (full) {
                v0 = x0[p];
                v1 = x1[p];
            } else {
                v0 = (g0     < nplanes) ? x0[p] : 0.f;
                v1 = (g0 + 1 < nplanes) ? x1[p] : 0.f;
            }
            u64 v;
            asm("mov.b64 %0, {%1,%2};" : "=l"(v)
                : "r"(__float_as_uint(v0)), "r"(__float_as_uint(v1)));
            tile[yy * PW + xx + 18] = v;
        }
    }

    // ---- per-thread line parameters (R11-verified mapping) ----
    const int lt = tid;
    int base, stride, fam, line;
    if (lt < 19)      { fam = 0; line = lt;      base = line + 18;      stride = PW;     }
    else if (lt < 38) { fam = 1; line = lt - 19; base = line * PW + 18; stride = 1;      }
    else if (lt < 75) { fam = 2; line = lt - 38; base = line;           stride = PW + 1; }
    else              { fam = 3; line = lt - 75; base = line + 18;      stride = PW - 1; }
    // fam2 (D1): cell k at (y=k, x=line-18+k) -> idx = k*PW + (line+k)
    // fam3 (D2): cell k at (y=k, x=line-k)    -> idx = k*PW + (line-k+18)

    // ---- weights straight from global (L2 broadcast), duplicated pairs ----
    const float* wsrc = weight + ((fam < 2) ? 0 : 18);
    u64 wr[18];
    #pragma unroll
    for (int i = 0; i < 18; i++) wr[i] = dupf(__ldg(wsrc + i));

    __syncthreads();

    // ---- preload line; transform: 342 FFMA2 on registers ----
    const u64* tp = tile;
    u64 ln[19];
    #pragma unroll
    for (int k = 0; k < BOARD; k++) ln[k] = tp[base + k * stride];

    u64 acc[19];
    #pragma unroll
    for (int j = 0; j < 19; j++) acc[j] = 0ull;

    #pragma unroll
    for (int k = 0; k < BOARD; k++) {
        const u64 v = ln[k];
        #pragma unroll
        for (int j = 0; j < BOARD; j++) {
            if (j == k) continue;
            const int d = (k > j) ? (k - j) : (j - k);
            FMA2(acc[j], v, wr[d - 1]);
        }
    }

    // ---- scatter line outputs (single family branch) ----
    if (fam == 0) {
        #pragma unroll
        for (int j = 0; j < BOARD; j++) bufV[j * BOARD + line] = acc[j];
    } else if (fam == 1) {
        #pragma unroll
        for (int j = 0; j < BOARD; j++) bufH[line * BOARD + j] = acc[j];
    } else if (fam == 2) {
        const int off = line - 18;            // x = j + off
        #pragma unroll
        for (int j = 0; j < BOARD; j++) {
            const int xx = j + off;
            if (xx >= 0 && xx < BOARD) bufD1[j * BOARD + xx] = acc[j];
        }
    } else {
        #pragma unroll
        for (int j = 0; j < BOARD; j++) {     // x = line - j
            const int xx = line - j;
            if (xx >= 0 && xx < BOARD) bufD2[j * BOARD + xx] = acc[j];
        }
    }

    __syncthreads();

    // ---- combine 4 partials, unpack, coalesced store per plane ----
    float* __restrict__ o0 = out + (size_t)g0 * NPOS;
    float* __restrict__ o1 = o0 + NPOS;
    #pragma unroll
    for (int it = 0; it < 4; it++) {
        const int p = tid + it * THREADS;
        if (p < NPOS) {
            u64 s = bufV[p];
            ADD2(s, bufH[p]);
            ADD2(s, bufD1[p]);
            ADD2(s, bufD2[p]);
            uint32_t p0, p1;
            asm("mov.b64 {%0,%1}, %2;" : "=r"(p0), "=r"(p1) : "l"(s));
            if (full) {
                o0[p] = __uint_as_float(p0);
                o1[p] = __uint_as_float(p1);
            } else {
                if (g0     < nplanes) o0[p] = __uint_as_float(p0);
                if (g0 + 1 < nplanes) o1[p] = __uint_as_float(p1);
            }
        }
    }
}

extern "C" void kernel_launch(void* const* d_in, const int* in_sizes, int n_in,
                              void* d_out, int out_size)
{
    const float* x      = (const float*)d_in[0];   // [32,64,19,19]
    const float* weight = (const float*)d_in[1];   // [2,18]
    float* out          = (float*)d_out;

    const int nplanes = in_sizes[0] / NPOS;        // 2048
    const int grid = (nplanes + PLANES - 1) / PLANES;   // 1024

    raycast_kernel<<<grid, THREADS>>>(x, weight, out, nplanes);
}